// round 1
// baseline (speedup 1.0000x reference)
#include <cuda_runtime.h>

#define NROWS 8192
#define DIM   64
#define BM    64
#define BN    64
#define NT    (NROWS / BM)   // 128 tiles per dim
#define KPAD  68             // padded m-stride for [k][m] smem tiles (16B-aligned, conflict-free)

// Scale folded into left operand: logits = cos * 20; ex2 arg = cos * 20 * log2(e)
#define SCALE_L2E 28.853900817779268f   // 20 * log2(e)
#define LN2F      0.6931471805599453f

// ---------------- device scratch (no allocs allowed) ----------------
__device__ float g_Ahat [NROWS * DIM];   // a / ||a||
__device__ float g_Phat [NROWS * DIM];   // p / ||p||
__device__ float g_Ahat2[NROWS * DIM];   // a / ||a|| * SCALE
__device__ float g_Phat2[NROWS * DIM];   // p / ||p|| * SCALE
__device__ float g_part [NROWS];         // partition accumulators
__device__ float g_pos  [NROWS];         // pos_logit_i = 20 * cos(a_i, p_i)

__device__ __forceinline__ float ex2f(float x) {
    float y;
    asm("ex2.approx.ftz.f32 %0, %1;" : "=f"(y) : "f"(x));
    return y;
}

// ---------------- kernel 1: normalize + zero accumulators ----------------
// grid: NROWS blocks of 64 threads. warp 0 -> anchor row, warp 1 -> positive row.
__global__ void prep_kernel(const float* __restrict__ A, const float* __restrict__ P) {
    int row  = blockIdx.x;
    int w    = threadIdx.x >> 5;
    int lane = threadIdx.x & 31;
    const float* src = w ? P : A;
    float x0 = src[row * DIM + lane];
    float x1 = src[row * DIM + lane + 32];
    float s = x0 * x0 + x1 * x1;
    #pragma unroll
    for (int o = 16; o; o >>= 1) s += __shfl_xor_sync(0xffffffffu, s, o);
    float r = rsqrtf(fmaxf(s, 1e-24f));
    float* dn = w ? g_Phat  : g_Ahat;
    float* ds = w ? g_Phat2 : g_Ahat2;
    dn[row * DIM + lane]      = x0 * r;
    dn[row * DIM + lane + 32] = x1 * r;
    ds[row * DIM + lane]      = x0 * r * SCALE_L2E;
    ds[row * DIM + lane + 32] = x1 * r * SCALE_L2E;
    if (threadIdx.x == 0) g_part[row] = 0.0f;
}

// ---------------- kernel 2: tiled pair GEMM + exp + row/col sums ----------------
// grid (NT, NT, 3):
//   z=0: E_ap = exp(20*cos(a_i, p_j)) over full matrix; rows -> part[i], cols -> part[j];
//        diagonal extracts pos_logit.
//   z=1: E_aa, upper triangle only (symmetric); each term credited to part[i] AND part[j].
//   z=2: E_pp, same as z=1.
__global__ void __launch_bounds__(256)
pair_kernel() {
    int type = blockIdx.z;
    int bi = blockIdx.y, bj = blockIdx.x;
    if (type > 0 && bj < bi) return;   // symmetric: upper-triangle tiles only

    const float* L = (type == 2) ? g_Phat2 : g_Ahat2;   // scaled left rows
    const float* R = (type == 1) ? g_Ahat  : g_Phat;    // unscaled right rows

    __shared__ float As[DIM][KPAD];   // As[k][m]
    __shared__ float Bs[DIM][KPAD];   // Bs[k][n]
    __shared__ float rsum[BM];
    __shared__ float csum[BN];

    int tid = threadIdx.x;
    const float* Lt = L + (size_t)bi * BM * DIM;   // contiguous 64x64 block
    const float* Rt = R + (size_t)bj * BN * DIM;

    // cooperative load + transpose into [k][m] layout
    #pragma unroll
    for (int it = 0; it < 4; ++it) {
        int f = tid + it * 256;        // float4 index 0..1023
        int m = f >> 4;                // row within tile
        int k = (f & 15) << 2;         // k chunk of 4
        float4 va = *(const float4*)(Lt + m * DIM + k);
        As[k][m] = va.x; As[k + 1][m] = va.y; As[k + 2][m] = va.z; As[k + 3][m] = va.w;
        float4 vb = *(const float4*)(Rt + m * DIM + k);
        Bs[k][m] = vb.x; Bs[k + 1][m] = vb.y; Bs[k + 2][m] = vb.z; Bs[k + 3][m] = vb.w;
    }
    if (tid < BM)            rsum[tid] = 0.0f;
    else if (tid < BM + BN)  csum[tid - BM] = 0.0f;
    __syncthreads();

    int ty = tid >> 4, tx = tid & 15;
    int r0 = ty * 4, c0 = tx * 4;

    float acc[4][4] = {};
    #pragma unroll 16
    for (int k = 0; k < DIM; ++k) {
        float4 a = *(const float4*)&As[k][r0];   // broadcast within half-warp
        float4 b = *(const float4*)&Bs[k][c0];   // contiguous, conflict-free
        acc[0][0] += a.x * b.x; acc[0][1] += a.x * b.y; acc[0][2] += a.x * b.z; acc[0][3] += a.x * b.w;
        acc[1][0] += a.y * b.x; acc[1][1] += a.y * b.y; acc[1][2] += a.y * b.z; acc[1][3] += a.y * b.w;
        acc[2][0] += a.z * b.x; acc[2][1] += a.z * b.y; acc[2][2] += a.z * b.z; acc[2][3] += a.z * b.w;
        acc[3][0] += a.w * b.x; acc[3][1] += a.w * b.y; acc[3][2] += a.w * b.z; acc[3][3] += a.w * b.w;
    }

    bool diagTile = (bi == bj);
    float lr[4] = {0.f, 0.f, 0.f, 0.f};
    float lc[4] = {0.f, 0.f, 0.f, 0.f};
    #pragma unroll
    for (int i = 0; i < 4; ++i) {
        #pragma unroll
        for (int j = 0; j < 4; ++j) {
            float v = ex2f(acc[i][j]);
            if (type > 0 && diagTile && (c0 + j) <= (r0 + i)) v = 0.0f;  // strict upper only
            lr[i] += v;
            lc[j] += v;
            if (type == 0 && diagTile && (r0 + i) == (c0 + j))
                g_pos[bi * BM + r0 + i] = acc[i][j] * LN2F;   // 20 * cos(a_i, p_i)
        }
    }

    #pragma unroll
    for (int i = 0; i < 4; ++i) atomicAdd(&rsum[r0 + i], lr[i]);
    #pragma unroll
    for (int j = 0; j < 4; ++j) atomicAdd(&csum[c0 + j], lc[j]);
    __syncthreads();

    // rows always credit part[bi*64 + r]; cols always credit part[bj*64 + c].
    // (z=0: rowsum+colsum of E_ap; z=1/2: symmetric double-credit of triangle terms.)
    if (tid < BM)           atomicAdd(&g_part[bi * BM + tid], rsum[tid]);
    else if (tid < BM + BN) atomicAdd(&g_part[bj * BN + (tid - BM)], csum[tid - BM]);
}

// ---------------- kernel 3: final reduction ----------------
// loss = -mean(pos_i - log(part_i)) = mean(log(part_i) - pos_i)
__global__ void loss_kernel(float* __restrict__ out) {
    __shared__ float red[256];
    float s = 0.0f;
    for (int i = threadIdx.x; i < NROWS; i += 256)
        s += __logf(g_part[i]) - g_pos[i];
    red[threadIdx.x] = s;
    __syncthreads();
    #pragma unroll
    for (int o = 128; o; o >>= 1) {
        if (threadIdx.x < o) red[threadIdx.x] += red[threadIdx.x + o];
        __syncthreads();
    }
    if (threadIdx.x == 0) out[0] = red[0] / (float)NROWS;
}

// ---------------- launch ----------------
extern "C" void kernel_launch(void* const* d_in, const int* in_sizes, int n_in,
                              void* d_out, int out_size) {
    const float* A = (const float*)d_in[0];
    const float* P = (const float*)d_in[1];
    prep_kernel<<<NROWS, 64>>>(A, P);
    dim3 grid(NT, NT, 3);
    pair_kernel<<<grid, 256>>>();
    loss_kernel<<<1, 256>>>((float*)d_out);
}

// round 3
// speedup vs baseline: 3.8506x; 3.8506x over previous
#include <cuda_runtime.h>
#include <cuda_bf16.h>
#include <cstdint>
#include <cmath>

#define NROWS 8192
#define XROWS 16384
#define DIM   64
#define BT    128                 // tile dim (square tiles)
#define NT    (XROWS / BT)        // 128 tile rows/cols
#define NTRI  (NT * (NT + 1) / 2) // 8256 upper-triangle tiles
#define LPAD  72                  // padded smem row stride (bf16 elems): conflict-free ldmatrix

#define SCALE_L2E 28.853900817779268f   // 20 * log2(e)

// ---------------- device scratch ----------------
__device__ __align__(16) __nv_bfloat16 g_Xs[XROWS * DIM];  // normalized * 20*log2(e)
__device__ __align__(16) __nv_bfloat16 g_Xn[XROWS * DIM];  // normalized
__device__ float g_part[XROWS];
__device__ float g_pos[NROWS];

static __device__ __forceinline__ uint32_t smem_u32(const void* p) {
    uint32_t a;
    asm("{ .reg .u64 t; cvta.to.shared.u64 t, %1; cvt.u32.u64 %0, t; }" : "=r"(a) : "l"(p));
    return a;
}
static __device__ __forceinline__ float ex2f(float x) {
    float y; asm("ex2.approx.ftz.f32 %0, %1;" : "=f"(y) : "f"(x)); return y;
}

// ---------------- kernel 1: normalize + bf16 (scaled & unscaled) + zero part ----------------
__global__ void prep_kernel(const float* __restrict__ A, const float* __restrict__ P) {
    int row  = blockIdx.x * 8 + (threadIdx.x >> 5);
    int lane = threadIdx.x & 31;
    const float* src = (row < NROWS) ? (A + (size_t)row * DIM)
                                     : (P + (size_t)(row - NROWS) * DIM);
    float x0 = src[lane], x1 = src[lane + 32];
    float s = x0 * x0 + x1 * x1;
    #pragma unroll
    for (int o = 16; o; o >>= 1) s += __shfl_xor_sync(0xffffffffu, s, o);
    float r = rsqrtf(fmaxf(s, 1e-24f));
    float v0 = x0 * r, v1 = x1 * r;
    g_Xn[(size_t)row * DIM + lane]      = __float2bfloat16(v0);
    g_Xn[(size_t)row * DIM + lane + 32] = __float2bfloat16(v1);
    g_Xs[(size_t)row * DIM + lane]      = __float2bfloat16(v0 * SCALE_L2E);
    g_Xs[(size_t)row * DIM + lane + 32] = __float2bfloat16(v1 * SCALE_L2E);
    if (lane == 0) g_part[row] = 0.0f;
}

// ---------------- kernel 2: exact fp32 positive logits ----------------
__global__ void pos_kernel(const float* __restrict__ A, const float* __restrict__ P) {
    int row  = blockIdx.x * 8 + (threadIdx.x >> 5);
    int lane = threadIdx.x & 31;
    float a0 = A[(size_t)row * DIM + lane], a1 = A[(size_t)row * DIM + lane + 32];
    float p0 = P[(size_t)row * DIM + lane], p1 = P[(size_t)row * DIM + lane + 32];
    float d  = a0 * p0 + a1 * p1;
    float sa = a0 * a0 + a1 * a1;
    float sp = p0 * p0 + p1 * p1;
    #pragma unroll
    for (int o = 16; o; o >>= 1) {
        d  += __shfl_xor_sync(0xffffffffu, d, o);
        sa += __shfl_xor_sync(0xffffffffu, sa, o);
        sp += __shfl_xor_sync(0xffffffffu, sp, o);
    }
    if (lane == 0)
        g_pos[row] = 20.0f * d / fmaxf(sqrtf(sa) * sqrtf(sp), 1e-6f);
}

// ---------------- kernel 3: upper-triangle tile GEMM (mma.sync) + exp + row/col sums ----------------
// Tile (bi,bj), bj>=bi, of M = exp(20*cos(X,X)). Each element credits part[row] and part[col]
// (symmetry). Global diagonal skipped (replaces -2*e^{1/T}).
__global__ void __launch_bounds__(256, 2) mma_kernel() {
    __shared__ __nv_bfloat16 Ls[BT][LPAD];
    __shared__ __nv_bfloat16 Rs[BT][LPAD];
    __shared__ float colsum[BT];

    // decode linear index -> upper-triangle (bi, bj)
    int t = blockIdx.x;
    int bi = (int)((2.0 * NT + 1.0 - sqrt((2.0 * NT + 1.0) * (2.0 * NT + 1.0) - 8.0 * (double)t)) * 0.5);
    while ((bi + 1) * (2 * NT - bi) / 2 <= t) ++bi;          // s(bi+1) <= t ?
    while (bi * (2 * NT - bi + 1) / 2 > t) --bi;             // s(bi)   >  t ?
    int bj = bi + (t - bi * (2 * NT - bi + 1) / 2);

    int tid = threadIdx.x, wid = tid >> 5, lane = tid & 31;

    const uint4* Lg = (const uint4*)(g_Xs + (size_t)bi * BT * DIM);
    const uint4* Rg = (const uint4*)(g_Xn + (size_t)bj * BT * DIM);
    #pragma unroll
    for (int it = 0; it < 4; ++it) {
        int f = tid + it * 256;        // 1024 uint4 per tile (8 per row)
        int r = f >> 3, kc = f & 7;
        *(uint4*)&Ls[r][kc * 8] = Lg[f];
        *(uint4*)&Rs[r][kc * 8] = Rg[f];
    }
    if (tid < BT) colsum[tid] = 0.0f;
    __syncthreads();

    bool diag = (bi == bj);
    int grow0 = bi * BT, gcol0 = bj * BT;

    // A fragments for this warp's 16-row strip (all of K=64): 4 k-chunks x ldmatrix.x4
    uint32_t a[4][4];
    {
        int r  = wid * 16 + (lane & 15);
        int kh = (lane >> 4) * 8;
        #pragma unroll
        for (int kc = 0; kc < 4; ++kc) {
            uint32_t addr = smem_u32(&Ls[r][kc * 16 + kh]);
            asm volatile("ldmatrix.sync.aligned.m8n8.x4.shared.b16 {%0,%1,%2,%3}, [%4];"
                         : "=r"(a[kc][0]), "=r"(a[kc][1]), "=r"(a[kc][2]), "=r"(a[kc][3])
                         : "r"(addr));
        }
    }

    int gid = lane >> 2, tig = lane & 3;
    int myrow0 = grow0 + wid * 16 + gid;   // rows for c0/c1
    int myrow1 = myrow0 + 8;               // rows for c2/c3
    float row0s = 0.0f, row1s = 0.0f;

    #pragma unroll
    for (int n = 0; n < 16; ++n) {
        uint32_t b[4][2];
        int brow = n * 8 + (lane & 7);
        int bkh  = ((lane >> 3) & 1) * 8;
        #pragma unroll
        for (int kc = 0; kc < 4; ++kc) {
            uint32_t addr = smem_u32(&Rs[brow][kc * 16 + bkh]);
            asm volatile("ldmatrix.sync.aligned.m8n8.x2.shared.b16 {%0,%1}, [%2];"
                         : "=r"(b[kc][0]), "=r"(b[kc][1]) : "r"(addr));
        }
        float c0 = 0.f, c1 = 0.f, c2 = 0.f, c3 = 0.f;
        #pragma unroll
        for (int kc = 0; kc < 4; ++kc) {
            asm volatile(
                "mma.sync.aligned.m16n8k16.row.col.f32.bf16.bf16.f32 "
                "{%0,%1,%2,%3}, {%4,%5,%6,%7}, {%8,%9}, {%0,%1,%2,%3};"
                : "+f"(c0), "+f"(c1), "+f"(c2), "+f"(c3)
                : "r"(a[kc][0]), "r"(a[kc][1]), "r"(a[kc][2]), "r"(a[kc][3]),
                  "r"(b[kc][0]), "r"(b[kc][1]));
        }
        // accumulators are 20*log2(e)*cos -> exp == ex2
        int gc0 = gcol0 + n * 8 + tig * 2;
        float e0 = ex2f(c0), e1 = ex2f(c1), e2 = ex2f(c2), e3 = ex2f(c3);
        if (diag) {   // strict upper triangle only (also removes global diagonal)
            if (gc0     <= myrow0) e0 = 0.0f;
            if (gc0 + 1 <= myrow0) e1 = 0.0f;
            if (gc0     <= myrow1) e2 = 0.0f;
            if (gc0 + 1 <= myrow1) e3 = 0.0f;
        }
        row0s += e0 + e1;
        row1s += e2 + e3;
        float cs0 = e0 + e2, cs1 = e1 + e3;
        #pragma unroll
        for (int o = 4; o < 32; o <<= 1) {
            cs0 += __shfl_xor_sync(0xffffffffu, cs0, o);
            cs1 += __shfl_xor_sync(0xffffffffu, cs1, o);
        }
        if (gid == 0) {   // lanes 0-3 hold warp-complete column sums for 8 cols
            atomicAdd(&colsum[n * 8 + tig * 2],     cs0);
            atomicAdd(&colsum[n * 8 + tig * 2 + 1], cs1);
        }
    }

    // row sums: reduce over the 4 lanes sharing each row
    #pragma unroll
    for (int o = 1; o < 4; o <<= 1) {
        row0s += __shfl_xor_sync(0xffffffffu, row0s, o);
        row1s += __shfl_xor_sync(0xffffffffu, row1s, o);
    }
    if (tig == 0) {
        atomicAdd(&g_part[myrow0], row0s);
        atomicAdd(&g_part[myrow1], row1s);
    }
    __syncthreads();
    if (tid < BT) atomicAdd(&g_part[gcol0 + tid], colsum[tid]);
}

// ---------------- kernel 4: final reduction ----------------
__global__ void loss_kernel(float* __restrict__ out) {
    __shared__ float red[256];
    float s = 0.0f;
    for (int i = threadIdx.x; i < NROWS; i += 256)
        s += __logf(g_part[i] + g_part[i + NROWS]) - g_pos[i];
    red[threadIdx.x] = s;
    __syncthreads();
    #pragma unroll
    for (int o = 128; o; o >>= 1) {
        if (threadIdx.x < o) red[threadIdx.x] += red[threadIdx.x + o];
        __syncthreads();
    }
    if (threadIdx.x == 0) out[0] = red[0] / (float)NROWS;
}

// ---------------- launch ----------------
extern "C" void kernel_launch(void* const* d_in, const int* in_sizes, int n_in,
                              void* d_out, int out_size) {
    const float* A = (const float*)d_in[0];
    const float* P = (const float*)d_in[1];
    prep_kernel<<<XROWS / 8, 256>>>(A, P);
    pos_kernel<<<NROWS / 8, 256>>>(A, P);
    mma_kernel<<<NTRI, 256>>>();
    loss_kernel<<<1, 256>>>((float*)d_out);
}

// round 4
// speedup vs baseline: 4.1169x; 1.0692x over previous
#include <cuda_runtime.h>
#include <cuda_bf16.h>
#include <cstdint>
#include <cmath>

#define NROWS 8192
#define XROWS 16384
#define DIM   64
#define BT    128                 // tile dim (square tiles)
#define NT    (XROWS / BT)        // 128 tile rows/cols
#define NTRI  (NT * (NT + 1) / 2) // 8256 upper-triangle tiles
#define LPAD  72                  // padded smem row stride (bf16): conflict-free ldmatrix

#define SCALE_L2E 28.853900817779268f   // 20 * log2(e)

// ---------------- device scratch ----------------
__device__ __align__(16) __nv_bfloat16 g_Xs[XROWS * DIM];  // normalized * 20*log2(e)
__device__ __align__(16) __nv_bfloat16 g_Xn[XROWS * DIM];  // normalized
__device__ float g_part[XROWS];
__device__ float g_pos[NROWS];
__device__ float g_loss;

static __device__ __forceinline__ uint32_t smem_u32(const void* p) {
    uint32_t a;
    asm("{ .reg .u64 t; cvta.to.shared.u64 t, %1; cvt.u32.u64 %0, t; }" : "=r"(a) : "l"(p));
    return a;
}
static __device__ __forceinline__ float ex2f(float x) {
    float y; asm("ex2.approx.ftz.f32 %0, %1;" : "=f"(y) : "f"(x)); return y;
}

// ---------------- kernel 1: fused normalize + bf16 + exact pos logit + zeroing ----------------
// one warp per pair-row i: handles a_i and p_i together.
__global__ void prep_kernel(const float* __restrict__ A, const float* __restrict__ P) {
    int row  = blockIdx.x * 8 + (threadIdx.x >> 5);
    int lane = threadIdx.x & 31;
    float a0 = A[(size_t)row * DIM + lane], a1 = A[(size_t)row * DIM + lane + 32];
    float p0 = P[(size_t)row * DIM + lane], p1 = P[(size_t)row * DIM + lane + 32];
    float sa = a0 * a0 + a1 * a1;
    float sp = p0 * p0 + p1 * p1;
    float d  = a0 * p0 + a1 * p1;
    #pragma unroll
    for (int o = 16; o; o >>= 1) {
        sa += __shfl_xor_sync(0xffffffffu, sa, o);
        sp += __shfl_xor_sync(0xffffffffu, sp, o);
        d  += __shfl_xor_sync(0xffffffffu, d,  o);
    }
    float ra = rsqrtf(fmaxf(sa, 1e-24f));
    float rp = rsqrtf(fmaxf(sp, 1e-24f));
    float va0 = a0 * ra, va1 = a1 * ra;
    float vp0 = p0 * rp, vp1 = p1 * rp;
    size_t ia = (size_t)row * DIM, ip = (size_t)(row + NROWS) * DIM;
    g_Xn[ia + lane]      = __float2bfloat16(va0);
    g_Xn[ia + lane + 32] = __float2bfloat16(va1);
    g_Xn[ip + lane]      = __float2bfloat16(vp0);
    g_Xn[ip + lane + 32] = __float2bfloat16(vp1);
    g_Xs[ia + lane]      = __float2bfloat16(va0 * SCALE_L2E);
    g_Xs[ia + lane + 32] = __float2bfloat16(va1 * SCALE_L2E);
    g_Xs[ip + lane]      = __float2bfloat16(vp0 * SCALE_L2E);
    g_Xs[ip + lane + 32] = __float2bfloat16(vp1 * SCALE_L2E);
    if (lane == 0) {
        g_pos[row] = 20.0f * d / fmaxf(sqrtf(sa) * sqrtf(sp), 1e-6f);
        g_part[row] = 0.0f;
        g_part[row + NROWS] = 0.0f;
    }
    if (blockIdx.x == 0 && threadIdx.x == 0) g_loss = 0.0f;
}

// ---------------- kernel 2: upper-triangle tile GEMM (mma.sync) + exp + row/col sums ----------------
// Tile (bi,bj), bj>=bi, of M = exp(20*cos(X,X)). Each element credits part[row] and part[col]
// (symmetry). Global diagonal skipped (replaces -2*e^{1/T}). Dual n-chains for ILP.
__global__ void __launch_bounds__(256, 2) mma_kernel() {
    __shared__ __nv_bfloat16 Ls[BT][LPAD];
    __shared__ __nv_bfloat16 Rs[BT][LPAD];
    __shared__ float colsum[BT];

    // decode linear index -> upper-triangle (bi, bj)
    int t = blockIdx.x;
    int bi = (int)((2.0 * NT + 1.0 - sqrt((2.0 * NT + 1.0) * (2.0 * NT + 1.0) - 8.0 * (double)t)) * 0.5);
    while ((bi + 1) * (2 * NT - bi) / 2 <= t) ++bi;
    while (bi * (2 * NT - bi + 1) / 2 > t) --bi;
    int bj = bi + (t - bi * (2 * NT - bi + 1) / 2);

    int tid = threadIdx.x, wid = tid >> 5, lane = tid & 31;

    const uint4* Lg = (const uint4*)(g_Xs + (size_t)bi * BT * DIM);
    const uint4* Rg = (const uint4*)(g_Xn + (size_t)bj * BT * DIM);
    #pragma unroll
    for (int it = 0; it < 4; ++it) {
        int f = tid + it * 256;        // 1024 uint4 per tile (8 per row)
        int r = f >> 3, kc = f & 7;
        *(uint4*)&Ls[r][kc * 8] = Lg[f];
        *(uint4*)&Rs[r][kc * 8] = Rg[f];
    }
    if (tid < BT) colsum[tid] = 0.0f;
    __syncthreads();

    bool diag = (bi == bj);
    int grow0 = bi * BT, gcol0 = bj * BT;

    // A fragments for this warp's 16-row strip (all of K=64)
    uint32_t a[4][4];
    {
        int r  = wid * 16 + (lane & 15);
        int kh = (lane >> 4) * 8;
        #pragma unroll
        for (int kc = 0; kc < 4; ++kc) {
            uint32_t addr = smem_u32(&Ls[r][kc * 16 + kh]);
            asm volatile("ldmatrix.sync.aligned.m8n8.x4.shared.b16 {%0,%1,%2,%3}, [%4];"
                         : "=r"(a[kc][0]), "=r"(a[kc][1]), "=r"(a[kc][2]), "=r"(a[kc][3])
                         : "r"(addr));
        }
    }

    int gid = lane >> 2, tig = lane & 3;
    int myrow0 = grow0 + wid * 16 + gid;
    int myrow1 = myrow0 + 8;
    float row0s = 0.0f, row1s = 0.0f;

    int brow_l = lane & 7;
    int bkh    = ((lane >> 3) & 1) * 8;

    #pragma unroll
    for (int n2 = 0; n2 < 8; ++n2) {
        // ---- load b fragments for both column groups (independent) ----
        uint32_t b[2][4][2];
        #pragma unroll
        for (int u = 0; u < 2; ++u) {
            int brow = (n2 * 2 + u) * 8 + brow_l;
            #pragma unroll
            for (int kc = 0; kc < 4; ++kc) {
                uint32_t addr = smem_u32(&Rs[brow][kc * 16 + bkh]);
                asm volatile("ldmatrix.sync.aligned.m8n8.x2.shared.b16 {%0,%1}, [%2];"
                             : "=r"(b[u][kc][0]), "=r"(b[u][kc][1]) : "r"(addr));
            }
        }
        // ---- two independent MMA chains ----
        float c[2][4] = {};
        #pragma unroll
        for (int kc = 0; kc < 4; ++kc) {
            #pragma unroll
            for (int u = 0; u < 2; ++u) {
                asm volatile(
                    "mma.sync.aligned.m16n8k16.row.col.f32.bf16.bf16.f32 "
                    "{%0,%1,%2,%3}, {%4,%5,%6,%7}, {%8,%9}, {%0,%1,%2,%3};"
                    : "+f"(c[u][0]), "+f"(c[u][1]), "+f"(c[u][2]), "+f"(c[u][3])
                    : "r"(a[kc][0]), "r"(a[kc][1]), "r"(a[kc][2]), "r"(a[kc][3]),
                      "r"(b[u][kc][0]), "r"(b[u][kc][1]));
            }
        }
        // ---- epilogue: exp + masks + row/col partial sums ----
        #pragma unroll
        for (int u = 0; u < 2; ++u) {
            int n = n2 * 2 + u;
            int gc0 = gcol0 + n * 8 + tig * 2;
            float e0 = ex2f(c[u][0]), e1 = ex2f(c[u][1]);
            float e2 = ex2f(c[u][2]), e3 = ex2f(c[u][3]);
            if (diag) {   // strict upper triangle only (also removes global diagonal)
                if (gc0     <= myrow0) e0 = 0.0f;
                if (gc0 + 1 <= myrow0) e1 = 0.0f;
                if (gc0     <= myrow1) e2 = 0.0f;
                if (gc0 + 1 <= myrow1) e3 = 0.0f;
            }
            row0s += e0 + e1;
            row1s += e2 + e3;
            float cs0 = e0 + e2, cs1 = e1 + e3;
            #pragma unroll
            for (int o = 4; o < 32; o <<= 1) {
                cs0 += __shfl_xor_sync(0xffffffffu, cs0, o);
                cs1 += __shfl_xor_sync(0xffffffffu, cs1, o);
            }
            if (gid == 0) {
                atomicAdd(&colsum[n * 8 + tig * 2],     cs0);
                atomicAdd(&colsum[n * 8 + tig * 2 + 1], cs1);
            }
        }
    }

    // row sums: reduce over the 4 lanes sharing each row
    #pragma unroll
    for (int o = 1; o < 4; o <<= 1) {
        row0s += __shfl_xor_sync(0xffffffffu, row0s, o);
        row1s += __shfl_xor_sync(0xffffffffu, row1s, o);
    }
    if (tig == 0) {
        atomicAdd(&g_part[myrow0], row0s);
        atomicAdd(&g_part[myrow1], row1s);
    }
    __syncthreads();
    if (tid < BT) atomicAdd(&g_part[gcol0 + tid], colsum[tid]);
}

// ---------------- kernel 3: parallel partial loss sums ----------------
__global__ void loss_partial_kernel() {
    __shared__ float wsum[8];
    int i = blockIdx.x * 256 + threadIdx.x;   // grid 32 x 256 covers NROWS exactly
    float s = __logf(g_part[i] + g_part[i + NROWS]) - g_pos[i];
    #pragma unroll
    for (int o = 16; o; o >>= 1) s += __shfl_xor_sync(0xffffffffu, s, o);
    int wid = threadIdx.x >> 5, lane = threadIdx.x & 31;
    if (lane == 0) wsum[wid] = s;
    __syncthreads();
    if (wid == 0) {
        float v = (lane < 8) ? wsum[lane] : 0.0f;
        #pragma unroll
        for (int o = 4; o; o >>= 1) v += __shfl_xor_sync(0xffffffffu, v, o);
        if (lane == 0) atomicAdd(&g_loss, v);
    }
}

// ---------------- kernel 4: finalize ----------------
__global__ void finalize_kernel(float* __restrict__ out) {
    out[0] = g_loss / (float)NROWS;
}

// ---------------- launch ----------------
extern "C" void kernel_launch(void* const* d_in, const int* in_sizes, int n_in,
                              void* d_out, int out_size) {
    const float* A = (const float*)d_in[0];
    const float* P = (const float*)d_in[1];
    prep_kernel<<<NROWS / 8, 256>>>(A, P);
    mma_kernel<<<NTRI, 256>>>();
    loss_partial_kernel<<<NROWS / 256, 256>>>();
    finalize_kernel<<<1, 1>>>((float*)d_out);
}

// round 5
// speedup vs baseline: 6.5604x; 1.5935x over previous
#include <cuda_runtime.h>
#include <cuda_bf16.h>
#include <cstdint>
#include <cmath>

#define NROWS 8192
#define XROWS 16384
#define DIM   64
#define BT    128                 // tile dim
#define NT    (XROWS / BT)        // 128 tiles per side
#define LPAD  72                  // padded smem row stride (bf16): conflict-free ldmatrix

#define SCALE_L2E 28.853900817779268f   // 20 * log2(e)

// ---------------- device scratch ----------------
__device__ __align__(16) __nv_bfloat16 g_Xs[XROWS * DIM];  // normalized * 20*log2(e)
__device__ __align__(16) __nv_bfloat16 g_Xn[XROWS * DIM];  // normalized
__device__ float g_part[XROWS];
__device__ float g_pos[NROWS];

static __device__ __forceinline__ uint32_t smem_u32(const void* p) {
    uint32_t a;
    asm("{ .reg .u64 t; cvta.to.shared.u64 t, %1; cvt.u32.u64 %0, t; }" : "=r"(a) : "l"(p));
    return a;
}
static __device__ __forceinline__ float ex2f(float x) {
    float y; asm("ex2.approx.ftz.f32 %0, %1;" : "=f"(y) : "f"(x)); return y;
}

// ---------------- kernel 1: fused normalize + bf16 + exact pos logit + zeroing ----------------
__global__ void prep_kernel(const float* __restrict__ A, const float* __restrict__ P,
                            float* __restrict__ out) {
    int row  = blockIdx.x * 8 + (threadIdx.x >> 5);
    int lane = threadIdx.x & 31;
    float a0 = A[(size_t)row * DIM + lane], a1 = A[(size_t)row * DIM + lane + 32];
    float p0 = P[(size_t)row * DIM + lane], p1 = P[(size_t)row * DIM + lane + 32];
    float sa = a0 * a0 + a1 * a1;
    float sp = p0 * p0 + p1 * p1;
    float d  = a0 * p0 + a1 * p1;
    #pragma unroll
    for (int o = 16; o; o >>= 1) {
        sa += __shfl_xor_sync(0xffffffffu, sa, o);
        sp += __shfl_xor_sync(0xffffffffu, sp, o);
        d  += __shfl_xor_sync(0xffffffffu, d,  o);
    }
    float ra = rsqrtf(fmaxf(sa, 1e-24f));
    float rp = rsqrtf(fmaxf(sp, 1e-24f));
    float va0 = a0 * ra, va1 = a1 * ra;
    float vp0 = p0 * rp, vp1 = p1 * rp;
    size_t ia = (size_t)row * DIM, ip = (size_t)(row + NROWS) * DIM;
    g_Xn[ia + lane]      = __float2bfloat16(va0);
    g_Xn[ia + lane + 32] = __float2bfloat16(va1);
    g_Xn[ip + lane]      = __float2bfloat16(vp0);
    g_Xn[ip + lane + 32] = __float2bfloat16(vp1);
    g_Xs[ia + lane]      = __float2bfloat16(va0 * SCALE_L2E);
    g_Xs[ia + lane + 32] = __float2bfloat16(va1 * SCALE_L2E);
    g_Xs[ip + lane]      = __float2bfloat16(vp0 * SCALE_L2E);
    g_Xs[ip + lane + 32] = __float2bfloat16(vp1 * SCALE_L2E);
    if (lane == 0) {
        g_pos[row] = 20.0f * d / fmaxf(sqrtf(sa) * sqrtf(sp), 1e-6f);
        g_part[row] = 0.0f;
        g_part[row + NROWS] = 0.0f;
    }
    if (blockIdx.x == 0 && threadIdx.x == 0) out[0] = 0.0f;
}

// ---------------- kernel 2: full-grid tile GEMM + exp + ROW sums only ----------------
// Tile (bi,bj) of M = exp(20*cos(X,X)); row sums accumulate partition directly.
// Global diagonal element skipped (replaces -2*e^{1/T}). No column reductions.
__global__ void __launch_bounds__(256, 2) mma_kernel() {
    __shared__ __nv_bfloat16 Ls[BT][LPAD];
    __shared__ __nv_bfloat16 Rs[BT][LPAD];

    int bi = blockIdx.y, bj = blockIdx.x;
    int tid = threadIdx.x, wid = tid >> 5, lane = tid & 31;

    const uint4* Lg = (const uint4*)(g_Xs + (size_t)bi * BT * DIM);
    const uint4* Rg = (const uint4*)(g_Xn + (size_t)bj * BT * DIM);
    #pragma unroll
    for (int it = 0; it < 4; ++it) {
        int f = tid + it * 256;        // 1024 uint4 per tile (8 per row)
        int r = f >> 3, kc = f & 7;
        *(uint4*)&Ls[r][kc * 8] = Lg[f];
        *(uint4*)&Rs[r][kc * 8] = Rg[f];
    }
    __syncthreads();

    bool diag = (bi == bj);
    int grow0 = bi * BT, gcol0 = bj * BT;

    // A fragments for this warp's 16-row strip (all of K=64)
    uint32_t a[4][4];
    {
        int r  = wid * 16 + (lane & 15);
        int kh = (lane >> 4) * 8;
        #pragma unroll
        for (int kc = 0; kc < 4; ++kc) {
            uint32_t addr = smem_u32(&Ls[r][kc * 16 + kh]);
            asm volatile("ldmatrix.sync.aligned.m8n8.x4.shared.b16 {%0,%1,%2,%3}, [%4];"
                         : "=r"(a[kc][0]), "=r"(a[kc][1]), "=r"(a[kc][2]), "=r"(a[kc][3])
                         : "r"(addr));
        }
    }

    int gid = lane >> 2, tig = lane & 3;
    int myrow0 = grow0 + wid * 16 + gid;   // rows for c0/c1
    int myrow1 = myrow0 + 8;               // rows for c2/c3
    float row0s = 0.0f, row1s = 0.0f;

    // B x4-ldmatrix lane mapping: lanes 0-7 -> (u=0,h=0), 8-15 -> (u=0,h=1),
    //                             16-23 -> (u=1,h=0), 24-31 -> (u=1,h=1)
    int b_u = (lane >> 4) & 1;
    int b_h = (lane >> 3) & 1;
    int b_r = lane & 7;

    #pragma unroll
    for (int n2 = 0; n2 < 8; ++n2) {
        uint32_t b[2][4][2];   // [ngroup u][kc][khalf]
        #pragma unroll
        for (int kc = 0; kc < 4; ++kc) {
            uint32_t addr = smem_u32(&Rs[n2 * 16 + b_u * 8 + b_r][kc * 16 + b_h * 8]);
            asm volatile("ldmatrix.sync.aligned.m8n8.x4.shared.b16 {%0,%1,%2,%3}, [%4];"
                         : "=r"(b[0][kc][0]), "=r"(b[0][kc][1]),
                           "=r"(b[1][kc][0]), "=r"(b[1][kc][1])
                         : "r"(addr));
        }
        float c[2][4] = {};
        #pragma unroll
        for (int kc = 0; kc < 4; ++kc) {
            #pragma unroll
            for (int u = 0; u < 2; ++u) {
                asm volatile(
                    "mma.sync.aligned.m16n8k16.row.col.f32.bf16.bf16.f32 "
                    "{%0,%1,%2,%3}, {%4,%5,%6,%7}, {%8,%9}, {%0,%1,%2,%3};"
                    : "+f"(c[u][0]), "+f"(c[u][1]), "+f"(c[u][2]), "+f"(c[u][3])
                    : "r"(a[kc][0]), "r"(a[kc][1]), "r"(a[kc][2]), "r"(a[kc][3]),
                      "r"(b[u][kc][0]), "r"(b[u][kc][1]));
            }
        }
        #pragma unroll
        for (int u = 0; u < 2; ++u) {
            float e0 = ex2f(c[u][0]), e1 = ex2f(c[u][1]);
            float e2 = ex2f(c[u][2]), e3 = ex2f(c[u][3]);
            if (diag) {   // zero the single global-diagonal element
                int gc0 = gcol0 + (n2 * 2 + u) * 8 + tig * 2;
                if (gc0     == myrow0) e0 = 0.0f;
                if (gc0 + 1 == myrow0) e1 = 0.0f;
                if (gc0     == myrow1) e2 = 0.0f;
                if (gc0 + 1 == myrow1) e3 = 0.0f;
            }
            row0s += e0 + e1;
            row1s += e2 + e3;
        }
    }

    // reduce over the 4 lanes (tig) sharing each row, then global accumulate
    #pragma unroll
    for (int o = 1; o < 4; o <<= 1) {
        row0s += __shfl_xor_sync(0xffffffffu, row0s, o);
        row1s += __shfl_xor_sync(0xffffffffu, row1s, o);
    }
    if (tig == 0) {
        atomicAdd(&g_part[myrow0], row0s);
        atomicAdd(&g_part[myrow1], row1s);
    }
}

// ---------------- kernel 3: loss reduction straight into d_out ----------------
__global__ void loss_kernel(float* __restrict__ out) {
    __shared__ float wsum[8];
    int i = blockIdx.x * 256 + threadIdx.x;   // grid 32 x 256 covers NROWS
    float s = __logf(g_part[i] + g_part[i + NROWS]) - g_pos[i];
    #pragma unroll
    for (int o = 16; o; o >>= 1) s += __shfl_xor_sync(0xffffffffu, s, o);
    int wid = threadIdx.x >> 5, lane = threadIdx.x & 31;
    if (lane == 0) wsum[wid] = s;
    __syncthreads();
    if (wid == 0) {
        float v = (lane < 8) ? wsum[lane] : 0.0f;
        #pragma unroll
        for (int o = 4; o; o >>= 1) v += __shfl_xor_sync(0xffffffffu, v, o);
        if (lane == 0) atomicAdd(out, v * (1.0f / (float)NROWS));
    }
}

// ---------------- launch ----------------
extern "C" void kernel_launch(void* const* d_in, const int* in_sizes, int n_in,
                              void* d_out, int out_size) {
    const float* A = (const float*)d_in[0];
    const float* P = (const float*)d_in[1];
    prep_kernel<<<NROWS / 8, 256>>>(A, P, (float*)d_out);
    mma_kernel<<<dim3(NT, NT), 256>>>();
    loss_kernel<<<NROWS / 256, 256>>>((float*)d_out);
}